// round 15
// baseline (speedup 1.0000x reference)
#include <cuda_runtime.h>
#include <cuda_fp16.h>
#include <cstdint>

#define H_DIM 1024
#define K_TOT 2048
#define M_TOT 4096
#define N_TOT 4096

#define BM 128
#define BN 128
#define BK 64                       // halves per k-stage
#define NSTAGE 3
#define A_STAGE_BYTES (BM * BK * 2)            // 16384
#define B_STAGE_BYTES (BN * BK * 2)            // 16384
#define STAGE_BYTES (A_STAGE_BYTES + B_STAGE_BYTES)   // 32768
#define SMEM_BYTES (NSTAGE * STAGE_BYTES)              // 98304

// fp16-staged operands
static __device__ __align__(256) __half g_Ah[(size_t)M_TOT * K_TOT];  // 16 MB
static __device__ __align__(256) __half g_Bh[(size_t)N_TOT * K_TOT];  // 16 MB

// ---------------------------------------------------------------------------
// helpers
// ---------------------------------------------------------------------------
__device__ __forceinline__ uint32_t smem_u32(const void* p) {
    uint32_t a;
    asm("{ .reg .u64 t; cvta.to.shared.u64 t, %1; cvt.u32.u64 %0, t; }" : "=r"(a) : "l"(p));
    return a;
}
__device__ __forceinline__ void cp16(uint32_t dst, const void* src) {
    asm volatile("cp.async.cg.shared.global [%0], [%1], 16;" ::"r"(dst), "l"(src));
}
__device__ __forceinline__ void ldsm4(uint32_t& r0, uint32_t& r1, uint32_t& r2, uint32_t& r3,
                                      uint32_t addr) {
    asm volatile("ldmatrix.sync.aligned.m8n8.x4.shared.b16 {%0,%1,%2,%3}, [%4];"
                 : "=r"(r0), "=r"(r1), "=r"(r2), "=r"(r3) : "r"(addr));
}
__device__ __forceinline__ void mma16816(float* c, const uint32_t* a, const uint32_t* b) {
    asm volatile(
        "mma.sync.aligned.m16n8k16.row.col.f32.f16.f16.f32 "
        "{%0,%1,%2,%3},{%4,%5,%6,%7},{%8,%9},{%0,%1,%2,%3};"
        : "+f"(c[0]), "+f"(c[1]), "+f"(c[2]), "+f"(c[3])
        : "r"(a[0]), "r"(a[1]), "r"(a[2]), "r"(a[3]), "r"(b[0]), "r"(b[1]));
}
__device__ __forceinline__ float sigf(float x) { return 1.0f / (1.0f + __expf(-x)); }

// ---------------------------------------------------------------------------
// Merged staging kernel (single launch; W and A phases overlap across grid):
//   z = 0..3 : W_g -> g_Bh[n][k] fp16, transposed, gate-interleaved
//                n(h,g) = ((h>>3)<<5) | (g<<3) | (h&7);  64k x 64h tile/block
//   z = 4..7 : [x | h_prev] -> g_Ah[m][0..2047] fp16 (8+8 elems per thread)
// ---------------------------------------------------------------------------
__global__ __launch_bounds__(256) void stage_all_kernel(
    const float* __restrict__ Wf, const float* __restrict__ Wi,
    const float* __restrict__ Wg, const float* __restrict__ Wo,
    const float* __restrict__ x, const float* __restrict__ hp) {
    const int tid = threadIdx.x;
    const int z = blockIdx.z;

    if (z < 4) {
        __shared__ float tile[64][65];
        const float* W = (z == 0) ? Wf : (z == 1) ? Wi : (z == 2) ? Wg : Wo;
        const int k0 = blockIdx.x * 64, h0 = blockIdx.y * 64;
        {
            const int r = tid >> 4;
            const int c4 = (tid & 15) * 4;
#pragma unroll
            for (int i = 0; i < 4; i++) {
                int row = r + i * 16;
                float4 v = *(const float4*)&W[(size_t)(k0 + row) * H_DIM + h0 + c4];
                tile[row][c4 + 0] = v.x;
                tile[row][c4 + 1] = v.y;
                tile[row][c4 + 2] = v.z;
                tile[row][c4 + 3] = v.w;
            }
        }
        __syncthreads();
        {
            const int hh = tid >> 2;
            const int ks0 = (tid & 3) * 16;
            const int h = h0 + hh;
            const int n = ((h >> 3) << 5) | (z << 3) | (h & 7);
#pragma unroll
            for (int seg = 0; seg < 2; seg++) {
                const int ks = ks0 + seg * 8;
                __half2 p[4];
#pragma unroll
                for (int j = 0; j < 4; j++)
                    p[j] = __floats2half2_rn(tile[ks + 2 * j][hh], tile[ks + 2 * j + 1][hh]);
                uint4 u;
                u.x = *(uint32_t*)&p[0]; u.y = *(uint32_t*)&p[1];
                u.z = *(uint32_t*)&p[2]; u.w = *(uint32_t*)&p[3];
                *(uint4*)&g_Bh[(size_t)n * K_TOT + k0 + ks] = u;
            }
        }
    } else {
        const int aid = (z - 4) * 512 + blockIdx.y * 32 + blockIdx.x;
        const int idx = aid * 256 + tid;
        const int m = idx >> 7;
        const int kq = (idx & 127) * 8;
        float4 vx0 = *(const float4*)&x[(size_t)m * 1024 + kq];
        float4 vx1 = *(const float4*)&x[(size_t)m * 1024 + kq + 4];
        float4 vh0 = *(const float4*)&hp[(size_t)m * 1024 + kq];
        float4 vh1 = *(const float4*)&hp[(size_t)m * 1024 + kq + 4];
        __half2 a0 = __floats2half2_rn(vx0.x, vx0.y), a1 = __floats2half2_rn(vx0.z, vx0.w);
        __half2 a2 = __floats2half2_rn(vx1.x, vx1.y), a3 = __floats2half2_rn(vx1.z, vx1.w);
        __half2 b0 = __floats2half2_rn(vh0.x, vh0.y), b1 = __floats2half2_rn(vh0.z, vh0.w);
        __half2 b2 = __floats2half2_rn(vh1.x, vh1.y), b3 = __floats2half2_rn(vh1.z, vh1.w);
        uint4 pa, pb;
        pa.x = *(uint32_t*)&a0; pa.y = *(uint32_t*)&a1;
        pa.z = *(uint32_t*)&a2; pa.w = *(uint32_t*)&a3;
        pb.x = *(uint32_t*)&b0; pb.y = *(uint32_t*)&b1;
        pb.z = *(uint32_t*)&b2; pb.w = *(uint32_t*)&b3;
        *(uint4*)&g_Ah[(size_t)m * 2048 + kq] = pa;
        *(uint4*)&g_Ah[(size_t)m * 2048 + 1024 + kq] = pb;
    }
}

// ---------------------------------------------------------------------------
// Main: fp16 mma.sync GEMM (128x128 CTA tile, 64x32 warp tile) + LSTM epilogue
// 8 warps: wm = wid&1 (2 x 64 rows), wn = wid>>1 (4 x 32 n-cols). occ = 2.
// Prefetch spread: 2 cp.async per kk-batch. Epilogue: batched c_prev loads
// (MLP=8) before the activation math.
// ---------------------------------------------------------------------------
__global__ __launch_bounds__(256, 2) void lstm_fp16_kernel(
    const float* __restrict__ c_prev,
    const float* __restrict__ bf, const float* __restrict__ bi,
    const float* __restrict__ bg, const float* __restrict__ bo,
    float* __restrict__ out) {

    extern __shared__ char smem[];
    const uint32_t sbase = smem_u32(smem);
    const int tid = threadIdx.x;
    const int lane = tid & 31;
    const int wid = tid >> 5;
    const int wm = wid & 1;
    const int wn = wid >> 1;

    const int bn0 = blockIdx.x * BN;
    const int bm0 = blockIdx.y * BM;

    // ---- per-lane ldmatrix address components (stage-invariant) ----
    const int q = lane >> 3;      // matrix index within x4
    const int lr = lane & 7;      // row within matrix
    uint32_t a_off[4], a_rm[4];
    uint32_t b_off[2], b_rm[2];
#pragma unroll
    for (int mt = 0; mt < 4; mt++) {
        int row = wm * 64 + mt * 16 + (q & 1) * 8 + lr;
        a_off[mt] = (uint32_t)row * 128;
        a_rm[mt] = (uint32_t)(row & 7);
    }
#pragma unroll
    for (int p = 0; p < 2; p++) {
        int row = wn * 32 + p * 16 + (q >> 1) * 8 + lr;
        b_off[p] = (uint32_t)row * 128;
        b_rm[p] = (uint32_t)(row & 7);
    }
    const uint32_t aqh = (uint32_t)(q >> 1);  // A chunk selector
    const uint32_t bql = (uint32_t)(q & 1);   // B chunk selector

    // ---- hoisted cp.async addressing (tid-invariant parts) ----
    uint32_t sw[4];      // swizzled smem byte offset within stage
    uint32_t goff[4];    // global offset in halves from tile base
#pragma unroll
    for (int i = 0; i < 4; i++) {
        int ch = i * 256 + tid;
        int r = ch >> 3, c = ch & 7;
        sw[i] = (uint32_t)(r * 128 + ((c ^ (r & 7)) << 4));
        goff[i] = (uint32_t)(r * K_TOT + c * 8);
    }
    const __half* Abase = g_Ah + (size_t)bm0 * K_TOT;
    const __half* Bbase = g_Bh + (size_t)bn0 * K_TOT;

    auto load_stage = [&](int kt, int s) {
        const uint32_t ab = sbase + s * STAGE_BYTES;
        const uint32_t bb = ab + A_STAGE_BYTES;
        const __half* Asrc = Abase + kt * BK;
        const __half* Bsrc = Bbase + kt * BK;
#pragma unroll
        for (int i = 0; i < 4; i++) {
            cp16(ab + sw[i], Asrc + goff[i]);
            cp16(bb + sw[i], Bsrc + goff[i]);
        }
    };
    // one A+B chunk pair (2 cp.async) — spread across kk batches
    auto load_part = [&](int kt, int s, int i) {
        const uint32_t ab = sbase + s * STAGE_BYTES;
        const __half* Asrc = Abase + kt * BK;
        const __half* Bsrc = Bbase + kt * BK;
        cp16(ab + sw[i], Asrc + goff[i]);
        cp16(ab + A_STAGE_BYTES + sw[i], Bsrc + goff[i]);
    };

    float acc[4][4][4];   // [m-tile][gate(=n-8-block)][frag]
#pragma unroll
    for (int mt = 0; mt < 4; mt++)
#pragma unroll
        for (int j = 0; j < 4; j++)
#pragma unroll
            for (int e = 0; e < 4; e++) acc[mt][j][e] = 0.0f;

    load_stage(0, 0);
    asm volatile("cp.async.commit_group;" ::: "memory");
    load_stage(1, 1);
    asm volatile("cp.async.commit_group;" ::: "memory");

    const int NKT = K_TOT / BK;  // 32
    int s = 0;    // stage being consumed
    int sl = 2;   // stage being loaded (kt+2)
    for (int kt = 0; kt < NKT; kt++) {
        if (kt < NKT - 1)
            asm volatile("cp.async.wait_group 1;" ::: "memory");  // stage kt ready
        else
            asm volatile("cp.async.wait_group 0;" ::: "memory");
        __syncthreads();  // stage kt visible; stage sl free (consumed at kt-1)

        const uint32_t As = sbase + s * STAGE_BYTES;
        const uint32_t Bs = As + A_STAGE_BYTES;
        const bool pf = (kt + 2 < NKT);

#pragma unroll
        for (int kk = 0; kk < 4; kk++) {
            uint32_t a[4][4], b[2][4];
            const uint32_t ca = (uint32_t)(kk * 2) + aqh;
            const uint32_t cb = (uint32_t)(kk * 2) + bql;
#pragma unroll
            for (int mt = 0; mt < 4; mt++)
                ldsm4(a[mt][0], a[mt][1], a[mt][2], a[mt][3],
                      As + a_off[mt] + ((ca ^ a_rm[mt]) << 4));
#pragma unroll
            for (int p = 0; p < 2; p++)
                ldsm4(b[p][0], b[p][1], b[p][2], b[p][3],
                      Bs + b_off[p] + ((cb ^ b_rm[p]) << 4));
            if (pf) load_part(kt + 2, sl, kk);   // 2 cp.async per batch
#pragma unroll
            for (int mt = 0; mt < 4; mt++)
#pragma unroll
                for (int p = 0; p < 2; p++) {
                    mma16816(acc[mt][2 * p + 0], a[mt], &b[p][0]);
                    mma16816(acc[mt][2 * p + 1], a[mt], &b[p][2]);
                }
        }
        if (pf) asm volatile("cp.async.commit_group;" ::: "memory");

        if (++s == 3) s = 0;
        if (++sl == 3) sl = 0;
    }

    // ---- fused LSTM epilogue ----
    // warp's 32 n-cols = 8 h values x 4 gates; j == gate, h = h_base + lq*2 + ho
    const int l4 = lane >> 2, lq = lane & 3;
    const int h = (bn0 >> 2) + wn * 8 + lq * 2;
    const float2 Bf = *(const float2*)&bf[h];
    const float2 Bi = *(const float2*)&bi[h];
    const float2 Bg = *(const float2*)&bg[h];
    const float2 Bo = *(const float2*)&bo[h];

    // batched c_prev loads (MLP=8) before any activation math
    const size_t cbase = (size_t)(bm0 + wm * 64 + l4) * H_DIM + h;
    float2 cpv[8];
#pragma unroll
    for (int mt = 0; mt < 4; mt++) {
#pragma unroll
        for (int rb = 0; rb < 2; rb++)
            cpv[mt * 2 + rb] = *(const float2*)&c_prev[cbase + (size_t)(mt * 16 + rb * 8) * H_DIM];
    }

#pragma unroll
    for (int mt = 0; mt < 4; mt++) {
#pragma unroll
        for (int rb = 0; rb < 2; rb++) {
            const int m = bm0 + wm * 64 + mt * 16 + l4 + rb * 8;
            const float2 cp = cpv[mt * 2 + rb];
            float hn[2], cn[2];
#pragma unroll
            for (int ho = 0; ho < 2; ho++) {
                const int e = rb * 2 + ho;
                float ft = sigf(acc[mt][0][e] + (ho ? Bf.y : Bf.x));
                float it = sigf(acc[mt][1][e] + (ho ? Bi.y : Bi.x));
                float gt = tanhf(acc[mt][2][e] + (ho ? Bg.y : Bg.x));
                float ot = sigf(acc[mt][3][e] + (ho ? Bo.y : Bo.x));
                cn[ho] = ft * (ho ? cp.y : cp.x) + it * gt;
                hn[ho] = ot * tanhf(cn[ho]);
            }
            *(float2*)&out[(size_t)m * H_DIM + h] = make_float2(hn[0], hn[1]);
            *(float2*)&out[(size_t)M_TOT * H_DIM + (size_t)m * H_DIM + h] =
                make_float2(cn[0], cn[1]);
        }
    }
}

// ---------------------------------------------------------------------------
extern "C" void kernel_launch(void* const* d_in, const int* in_sizes, int n_in,
                              void* d_out, int out_size) {
    const float* x      = (const float*)d_in[0];
    const float* h_prev = (const float*)d_in[1];
    const float* c_prev = (const float*)d_in[2];
    const float* Wf = (const float*)d_in[3]; const float* bf = (const float*)d_in[4];
    const float* Wi = (const float*)d_in[5]; const float* bi = (const float*)d_in[6];
    const float* Wg = (const float*)d_in[7]; const float* bg = (const float*)d_in[8];
    const float* Wo = (const float*)d_in[9]; const float* bo = (const float*)d_in[10];
    float* out = (float*)d_out;

    // z 0..3: W staging (32x16 tiles of 64x64); z 4..7: A staging (2048 vblocks)
    stage_all_kernel<<<dim3(32, 16, 8), 256>>>(Wf, Wi, Wg, Wo, x, h_prev);

    cudaFuncSetAttribute(lstm_fp16_kernel,
                         cudaFuncAttributeMaxDynamicSharedMemorySize, SMEM_BYTES);
    lstm_fp16_kernel<<<dim3(N_TOT / BN, M_TOT / BM), 256, SMEM_BYTES>>>(
        c_prev, bf, bi, bg, bo, out);
}

// round 16
// speedup vs baseline: 1.1077x; 1.1077x over previous
#include <cuda_runtime.h>
#include <cuda_fp16.h>
#include <cstdint>

#define H_DIM 1024
#define K_TOT 2048
#define M_TOT 4096
#define N_TOT 4096

#define BM 128
#define BN 128
#define BK 64                       // halves per k-stage
#define NSTAGE 3
#define A_STAGE_BYTES (BM * BK * 2)            // 16384
#define B_STAGE_BYTES (BN * BK * 2)            // 16384
#define STAGE_BYTES (A_STAGE_BYTES + B_STAGE_BYTES)   // 32768
#define SMEM_BYTES (NSTAGE * STAGE_BYTES)              // 98304

// fp16-staged operands
static __device__ __align__(256) __half g_Ah[(size_t)M_TOT * K_TOT];  // 16 MB
static __device__ __align__(256) __half g_Bh[(size_t)N_TOT * K_TOT];  // 16 MB

// ---------------------------------------------------------------------------
// helpers
// ---------------------------------------------------------------------------
__device__ __forceinline__ uint32_t smem_u32(const void* p) {
    uint32_t a;
    asm("{ .reg .u64 t; cvta.to.shared.u64 t, %1; cvt.u32.u64 %0, t; }" : "=r"(a) : "l"(p));
    return a;
}
__device__ __forceinline__ void cp16(uint32_t dst, const void* src) {
    asm volatile("cp.async.cg.shared.global [%0], [%1], 16;" ::"r"(dst), "l"(src));
}
__device__ __forceinline__ void ldsm4(uint32_t& r0, uint32_t& r1, uint32_t& r2, uint32_t& r3,
                                      uint32_t addr) {
    asm volatile("ldmatrix.sync.aligned.m8n8.x4.shared.b16 {%0,%1,%2,%3}, [%4];"
                 : "=r"(r0), "=r"(r1), "=r"(r2), "=r"(r3) : "r"(addr));
}
__device__ __forceinline__ void mma16816(float* c, const uint32_t* a, const uint32_t* b) {
    asm volatile(
        "mma.sync.aligned.m16n8k16.row.col.f32.f16.f16.f32 "
        "{%0,%1,%2,%3},{%4,%5,%6,%7},{%8,%9},{%0,%1,%2,%3};"
        : "+f"(c[0]), "+f"(c[1]), "+f"(c[2]), "+f"(c[3])
        : "r"(a[0]), "r"(a[1]), "r"(a[2]), "r"(a[3]), "r"(b[0]), "r"(b[1]));
}
__device__ __forceinline__ float sigf(float x) { return 1.0f / (1.0f + __expf(-x)); }

// ---------------------------------------------------------------------------
// Merged staging kernel (single launch; W and A phases overlap across grid):
//   z = 0..3 : W_g -> g_Bh[n][k] fp16, transposed, gate-interleaved
//                n(h,g) = ((h>>3)<<5) | (g<<3) | (h&7);  64k x 64h tile/block
//   z = 4..7 : [x | h_prev] -> g_Ah[m][0..2047] fp16 (8+8 elems per thread)
// ---------------------------------------------------------------------------
__global__ __launch_bounds__(256) void stage_all_kernel(
    const float* __restrict__ Wf, const float* __restrict__ Wi,
    const float* __restrict__ Wg, const float* __restrict__ Wo,
    const float* __restrict__ x, const float* __restrict__ hp) {
    const int tid = threadIdx.x;
    const int z = blockIdx.z;

    if (z < 4) {
        __shared__ float tile[64][65];
        const float* W = (z == 0) ? Wf : (z == 1) ? Wi : (z == 2) ? Wg : Wo;
        const int k0 = blockIdx.x * 64, h0 = blockIdx.y * 64;
        {
            const int r = tid >> 4;
            const int c4 = (tid & 15) * 4;
#pragma unroll
            for (int i = 0; i < 4; i++) {
                int row = r + i * 16;
                float4 v = *(const float4*)&W[(size_t)(k0 + row) * H_DIM + h0 + c4];
                tile[row][c4 + 0] = v.x;
                tile[row][c4 + 1] = v.y;
                tile[row][c4 + 2] = v.z;
                tile[row][c4 + 3] = v.w;
            }
        }
        __syncthreads();
        {
            const int hh = tid >> 2;
            const int ks0 = (tid & 3) * 16;
            const int h = h0 + hh;
            const int n = ((h >> 3) << 5) | (z << 3) | (h & 7);
#pragma unroll
            for (int seg = 0; seg < 2; seg++) {
                const int ks = ks0 + seg * 8;
                __half2 p[4];
#pragma unroll
                for (int j = 0; j < 4; j++)
                    p[j] = __floats2half2_rn(tile[ks + 2 * j][hh], tile[ks + 2 * j + 1][hh]);
                uint4 u;
                u.x = *(uint32_t*)&p[0]; u.y = *(uint32_t*)&p[1];
                u.z = *(uint32_t*)&p[2]; u.w = *(uint32_t*)&p[3];
                *(uint4*)&g_Bh[(size_t)n * K_TOT + k0 + ks] = u;
            }
        }
    } else {
        const int aid = (z - 4) * 512 + blockIdx.y * 32 + blockIdx.x;
        const int idx = aid * 256 + tid;
        const int m = idx >> 7;
        const int kq = (idx & 127) * 8;
        float4 vx0 = *(const float4*)&x[(size_t)m * 1024 + kq];
        float4 vx1 = *(const float4*)&x[(size_t)m * 1024 + kq + 4];
        float4 vh0 = *(const float4*)&hp[(size_t)m * 1024 + kq];
        float4 vh1 = *(const float4*)&hp[(size_t)m * 1024 + kq + 4];
        __half2 a0 = __floats2half2_rn(vx0.x, vx0.y), a1 = __floats2half2_rn(vx0.z, vx0.w);
        __half2 a2 = __floats2half2_rn(vx1.x, vx1.y), a3 = __floats2half2_rn(vx1.z, vx1.w);
        __half2 b0 = __floats2half2_rn(vh0.x, vh0.y), b1 = __floats2half2_rn(vh0.z, vh0.w);
        __half2 b2 = __floats2half2_rn(vh1.x, vh1.y), b3 = __floats2half2_rn(vh1.z, vh1.w);
        uint4 pa, pb;
        pa.x = *(uint32_t*)&a0; pa.y = *(uint32_t*)&a1;
        pa.z = *(uint32_t*)&a2; pa.w = *(uint32_t*)&a3;
        pb.x = *(uint32_t*)&b0; pb.y = *(uint32_t*)&b1;
        pb.z = *(uint32_t*)&b2; pb.w = *(uint32_t*)&b3;
        *(uint4*)&g_Ah[(size_t)m * 2048 + kq] = pa;
        *(uint4*)&g_Ah[(size_t)m * 2048 + 1024 + kq] = pb;
    }
}

// ---------------------------------------------------------------------------
// Main: fp16 mma.sync GEMM (128x128 CTA tile, 64x32 warp tile) + LSTM epilogue
// 8 warps: wm = wid&1 (2 x 64 rows), wn = wid>>1 (4 x 32 n-cols). occ = 2.
// kt-loop unrolled by the stage period (3): all stage offsets are immediates,
// no stage counters in the hot loop. Prefetch spread 2 cp.async per kk-batch.
// ---------------------------------------------------------------------------
__global__ __launch_bounds__(256, 2) void lstm_fp16_kernel(
    const float* __restrict__ c_prev,
    const float* __restrict__ bf, const float* __restrict__ bi,
    const float* __restrict__ bg, const float* __restrict__ bo,
    float* __restrict__ out) {

    extern __shared__ char smem[];
    const uint32_t sbase = smem_u32(smem);
    const int tid = threadIdx.x;
    const int lane = tid & 31;
    const int wid = tid >> 5;
    const int wm = wid & 1;
    const int wn = wid >> 1;

    const int bn0 = blockIdx.x * BN;
    const int bm0 = blockIdx.y * BM;

    // ---- per-lane ldmatrix address components (stage-invariant) ----
    const int q = lane >> 3;      // matrix index within x4
    const int lr = lane & 7;      // row within matrix
    uint32_t a_off[4], a_rm[4];
    uint32_t b_off[2], b_rm[2];
#pragma unroll
    for (int mt = 0; mt < 4; mt++) {
        int row = wm * 64 + mt * 16 + (q & 1) * 8 + lr;
        a_off[mt] = (uint32_t)row * 128;
        a_rm[mt] = (uint32_t)(row & 7);
    }
#pragma unroll
    for (int p = 0; p < 2; p++) {
        int row = wn * 32 + p * 16 + (q >> 1) * 8 + lr;
        b_off[p] = (uint32_t)row * 128;
        b_rm[p] = (uint32_t)(row & 7);
    }
    const uint32_t aqh = (uint32_t)(q >> 1);  // A chunk selector
    const uint32_t bql = (uint32_t)(q & 1);   // B chunk selector

    // ---- hoisted cp.async addressing (tid-invariant parts) ----
    uint32_t sw[4];      // swizzled smem byte offset within stage
    uint32_t goff[4];    // global offset in halves from tile base
#pragma unroll
    for (int i = 0; i < 4; i++) {
        int ch = i * 256 + tid;
        int r = ch >> 3, c = ch & 7;
        sw[i] = (uint32_t)(r * 128 + ((c ^ (r & 7)) << 4));
        goff[i] = (uint32_t)(r * K_TOT + c * 8);
    }
    const __half* Abase = g_Ah + (size_t)bm0 * K_TOT;
    const __half* Bbase = g_Bh + (size_t)bn0 * K_TOT;

    auto load_stage = [&](int kt, uint32_t sOff) {
        const uint32_t ab = sbase + sOff;
        const uint32_t bb = ab + A_STAGE_BYTES;
        const __half* Asrc = Abase + kt * BK;
        const __half* Bsrc = Bbase + kt * BK;
#pragma unroll
        for (int i = 0; i < 4; i++) {
            cp16(ab + sw[i], Asrc + goff[i]);
            cp16(bb + sw[i], Bsrc + goff[i]);
        }
    };
    // one A+B chunk pair (2 cp.async) — spread across kk batches
    auto load_part = [&](int kt, uint32_t sOff, int i) {
        const uint32_t ab = sbase + sOff;
        const __half* Asrc = Abase + kt * BK;
        const __half* Bsrc = Bbase + kt * BK;
        cp16(ab + sw[i], Asrc + goff[i]);
        cp16(ab + A_STAGE_BYTES + sw[i], Bsrc + goff[i]);
    };

    float acc[4][4][4];   // [m-tile][gate(=n-8-block)][frag]
#pragma unroll
    for (int mt = 0; mt < 4; mt++)
#pragma unroll
        for (int j = 0; j < 4; j++)
#pragma unroll
            for (int e = 0; e < 4; e++) acc[mt][j][e] = 0.0f;

    // one kt step: wait, sync, 4 kk batches (ldsm + spread prefetch + mma)
    auto ktstep = [&](int kt, uint32_t sOffC, uint32_t sOffP, bool pf, bool lastwait) {
        if (!lastwait)
            asm volatile("cp.async.wait_group 1;" ::: "memory");
        else
            asm volatile("cp.async.wait_group 0;" ::: "memory");
        __syncthreads();  // stage kt visible; prefetch target stage free

        const uint32_t As = sbase + sOffC;
        const uint32_t Bs = As + A_STAGE_BYTES;
#pragma unroll
        for (int kk = 0; kk < 4; kk++) {
            uint32_t a[4][4], b[2][4];
            const uint32_t ca = (uint32_t)(kk * 2) + aqh;
            const uint32_t cb = (uint32_t)(kk * 2) + bql;
#pragma unroll
            for (int mt = 0; mt < 4; mt++)
                ldsm4(a[mt][0], a[mt][1], a[mt][2], a[mt][3],
                      As + a_off[mt] + ((ca ^ a_rm[mt]) << 4));
#pragma unroll
            for (int p = 0; p < 2; p++)
                ldsm4(b[p][0], b[p][1], b[p][2], b[p][3],
                      Bs + b_off[p] + ((cb ^ b_rm[p]) << 4));
            if (pf) load_part(kt + 2, sOffP, kk);   // 2 cp.async per batch
#pragma unroll
            for (int mt = 0; mt < 4; mt++)
#pragma unroll
                for (int p = 0; p < 2; p++) {
                    mma16816(acc[mt][2 * p + 0], a[mt], &b[p][0]);
                    mma16816(acc[mt][2 * p + 1], a[mt], &b[p][2]);
                }
        }
        if (pf) asm volatile("cp.async.commit_group;" ::: "memory");
    };

    load_stage(0, 0);
    asm volatile("cp.async.commit_group;" ::: "memory");
    load_stage(1, STAGE_BYTES);
    asm volatile("cp.async.commit_group;" ::: "memory");

    // NKT = 32 = 3*10 + 2; stage(kt) = kt%3, prefetch stage = (kt+2)%3
#pragma unroll 1
    for (int kt = 0; kt < 30; kt += 3) {
        ktstep(kt + 0, 0 * STAGE_BYTES, 2 * STAGE_BYTES, true, false);
        ktstep(kt + 1, 1 * STAGE_BYTES, 0 * STAGE_BYTES, true, false);
        ktstep(kt + 2, 2 * STAGE_BYTES, 1 * STAGE_BYTES, true, false);
    }
    ktstep(30, 0 * STAGE_BYTES, 0, false, false);
    ktstep(31, 1 * STAGE_BYTES, 0, false, true);

    // ---- fused LSTM epilogue (all in registers) ----
    // warp's 32 n-cols = 8 h values x 4 gates; j == gate, h = h_base + lq*2 + ho
    const int l4 = lane >> 2, lq = lane & 3;
    const int h = (bn0 >> 2) + wn * 8 + lq * 2;
    const float2 Bf = *(const float2*)&bf[h];
    const float2 Bi = *(const float2*)&bi[h];
    const float2 Bg = *(const float2*)&bg[h];
    const float2 Bo = *(const float2*)&bo[h];
#pragma unroll
    for (int mt = 0; mt < 4; mt++) {
#pragma unroll
        for (int rb = 0; rb < 2; rb++) {
            const int m = bm0 + wm * 64 + mt * 16 + l4 + rb * 8;
            const float2 cp = *(const float2*)&c_prev[(size_t)m * H_DIM + h];
            float hn[2], cn[2];
#pragma unroll
            for (int ho = 0; ho < 2; ho++) {
                const int e = rb * 2 + ho;
                float ft = sigf(acc[mt][0][e] + (ho ? Bf.y : Bf.x));
                float it = sigf(acc[mt][1][e] + (ho ? Bi.y : Bi.x));
                float gt = tanhf(acc[mt][2][e] + (ho ? Bg.y : Bg.x));
                float ot = sigf(acc[mt][3][e] + (ho ? Bo.y : Bo.x));
                cn[ho] = ft * (ho ? cp.y : cp.x) + it * gt;
                hn[ho] = ot * tanhf(cn[ho]);
            }
            *(float2*)&out[(size_t)m * H_DIM + h] = make_float2(hn[0], hn[1]);
            *(float2*)&out[(size_t)M_TOT * H_DIM + (size_t)m * H_DIM + h] =
                make_float2(cn[0], cn[1]);
        }
    }
}

// ---------------------------------------------------------------------------
extern "C" void kernel_launch(void* const* d_in, const int* in_sizes, int n_in,
                              void* d_out, int out_size) {
    const float* x      = (const float*)d_in[0];
    const float* h_prev = (const float*)d_in[1];
    const float* c_prev = (const float*)d_in[2];
    const float* Wf = (const float*)d_in[3]; const float* bf = (const float*)d_in[4];
    const float* Wi = (const float*)d_in[5]; const float* bi = (const float*)d_in[6];
    const float* Wg = (const float*)d_in[7]; const float* bg = (const float*)d_in[8];
    const float* Wo = (const float*)d_in[9]; const float* bo = (const float*)d_in[10];
    float* out = (float*)d_out;

    // z 0..3: W staging (32x16 tiles of 64x64); z 4..7: A staging (2048 vblocks)
    stage_all_kernel<<<dim3(32, 16, 8), 256>>>(Wf, Wi, Wg, Wo, x, h_prev);

    cudaFuncSetAttribute(lstm_fp16_kernel,
                         cudaFuncAttributeMaxDynamicSharedMemorySize, SMEM_BYTES);
    lstm_fp16_kernel<<<dim3(N_TOT / BN, M_TOT / BM), 256, SMEM_BYTES>>>(
        c_prev, bf, bi, bg, bo, out);
}